// round 4
// baseline (speedup 1.0000x reference)
#include <cuda_runtime.h>
#include <stdint.h>

// EdgeNetwork: y[e,i] = sum_j ( sum_b bond[e,b]*K[b,i*32+j] + bias[i*32+j] ) * atom[nbr[e], j]
// out = segment_sum(y, src[e])
//
// Shapes: atom (Na,32) f32, bond (E,16) f32, pair (E,2) int32, K (16,1024) f32,
// bias (1024) f32, out (Na,32) f32.

#define ATOM_DIM 32
#define BOND_DIM 16
#define NTHREADS 256
#define NWARPS   8
#define G        4              // edges per warp (register-resident bond coeffs)
#define EPP      (NWARPS * G)   // 32 edges per pass
#define NJP      (ATOM_DIM / 2) // 16 j-pairs

// dynamic smem layout (floats):
//   Ksh    : BOND_DIM*NJP*ATOM_DIM*2 = 16384   (64 KB)
//   biassh : NJP*ATOM_DIM*2          = 1024    (4 KB)
//   nbsh   : EPP*ATOM_DIM            = 1024    (4 KB)
//   bondsh : EPP*BOND_DIM            = 512     (2 KB)
//   dstsh  : EPP ints                = 32      (128 B)
#define OFF_K    0
#define OFF_BIA  (BOND_DIM * NJP * ATOM_DIM * 2)
#define OFF_NB   (OFF_BIA + NJP * ATOM_DIM * 2)
#define OFF_BOND (OFF_NB + EPP * ATOM_DIM)
#define OFF_DST  (OFF_BOND + EPP * BOND_DIM)
#define SMEM_FLOATS (OFF_DST + EPP)
#define SMEM_BYTES  (SMEM_FLOATS * 4)

// ---- packed f32x2 helpers (Blackwell FFMA2 path, PTX-only) ----
__device__ __forceinline__ unsigned long long pack2(float a, float b) {
    unsigned long long r;
    asm("mov.b64 %0, {%1,%2};" : "=l"(r) : "f"(a), "f"(b));
    return r;
}
__device__ __forceinline__ unsigned long long fma2(unsigned long long a,
                                                   unsigned long long b,
                                                   unsigned long long c) {
    unsigned long long d;
    asm("fma.rn.f32x2 %0, %1, %2, %3;" : "=l"(d) : "l"(a), "l"(b), "l"(c));
    return d;
}
__device__ __forceinline__ float hsum2(unsigned long long v) {
    float a, b;
    asm("mov.b64 {%0,%1}, %2;" : "=f"(a), "=f"(b) : "l"(v));
    return a + b;
}

__global__ __launch_bounds__(NTHREADS, 1)
void edge_network_kernel(const float* __restrict__ atom,
                         const float* __restrict__ bond,
                         const int* __restrict__ pair,
                         const float* __restrict__ Kmat,
                         const float* __restrict__ bias,
                         float* __restrict__ out,
                         int n_edges, int n_passes)
{
    extern __shared__ __align__(16) float smem[];
    float* Ksh    = smem + OFF_K;     // [b][jp][i][h] pair-packed, conflict-free 8B lane reads
    float* biassh = smem + OFF_BIA;   // [jp][i][h]
    float* nbsh   = smem + OFF_NB;    // [e_l][j]
    float* bondsh = smem + OFF_BOND;  // [e_l][b]
    int*   dstsh  = (int*)(smem + OFF_DST);

    const int tid  = threadIdx.x;
    const int w    = tid >> 5;
    const int lane = tid & 31;

    // ---- one-time: load K (transposed to pair-packed layout) + bias ----
    for (int idx = tid; idx < BOND_DIM * 1024; idx += NTHREADS) {
        int b   = idx >> 10;
        int rem = idx & 1023;
        int i   = rem >> 5;
        int j   = rem & 31;
        Ksh[(((b * NJP) + (j >> 1)) * ATOM_DIM + i) * 2 + (j & 1)] = Kmat[idx];
    }
    for (int idx = tid; idx < 1024; idx += NTHREADS) {
        int i = idx >> 5;
        int j = idx & 31;
        biassh[((j >> 1) * ATOM_DIM + i) * 2 + (j & 1)] = bias[idx];
    }

    unsigned long long bond2[G][BOND_DIM];  // {v,v}-packed bond coeffs, 4 edges
    unsigned long long acc2[G];

    for (int pass = blockIdx.x; pass < n_passes; pass += gridDim.x) {
        const int e0 = pass * EPP;
        __syncthreads();  // protect staging smem from previous pass's compute (also orders K load, iter 0)

        // ---- stage: neighbor rows (gather), bond rows, dst indices ----
        {
            int e_l = tid >> 3;        // 32 edges x 8 threads
            int c   = (tid & 7) * 4;
            int e   = e0 + e_l;
            float4 v = make_float4(0.f, 0.f, 0.f, 0.f);
            if (e < n_edges) {
                int nidx = pair[2 * e + 1];
                v = *reinterpret_cast<const float4*>(atom + (long long)nidx * ATOM_DIM + c);
            }
            *reinterpret_cast<float4*>(&nbsh[e_l * ATOM_DIM + c]) = v;
        }
        if (tid < EPP * BOND_DIM / 4) {  // 128 threads: bond rows
            int e_l = tid >> 2;
            int c   = (tid & 3) * 4;
            int e   = e0 + e_l;
            float4 v = make_float4(0.f, 0.f, 0.f, 0.f);
            if (e < n_edges)
                v = *reinterpret_cast<const float4*>(bond + (long long)e * BOND_DIM + c);
            *reinterpret_cast<float4*>(&bondsh[e_l * BOND_DIM + c]) = v;
        } else if (tid < EPP * BOND_DIM / 4 + EPP) {  // 32 threads: dst indices
            int e_l = tid - EPP * BOND_DIM / 4;
            int e   = e0 + e_l;
            dstsh[e_l] = (e < n_edges) ? pair[2 * e] : -1;
        }
        __syncthreads();

        // ---- bond coeffs -> packed registers ----
        #pragma unroll
        for (int g = 0; g < G; g++) {
            int e_l = w * G + g;
            #pragma unroll
            for (int b = 0; b < BOND_DIM; b++) {
                float v = bondsh[e_l * BOND_DIM + b];
                bond2[g][b] = pack2(v, v);
            }
            acc2[g] = 0ull;
        }

        // ---- main compute: per j-pair, build edge-matrix entries, dot with neighbor ----
        #pragma unroll 4
        for (int jp = 0; jp < NJP; jp++) {
            unsigned long long bia =
                *reinterpret_cast<const unsigned long long*>(&biassh[(jp * ATOM_DIM + lane) * 2]);
            unsigned long long m0 = bia, m1 = bia, m2 = bia, m3 = bia;
            #pragma unroll
            for (int b = 0; b < BOND_DIM; b++) {
                unsigned long long kv = *reinterpret_cast<const unsigned long long*>(
                    &Ksh[((b * NJP + jp) * ATOM_DIM + lane) * 2]);
                m0 = fma2(bond2[0][b], kv, m0);
                m1 = fma2(bond2[1][b], kv, m1);
                m2 = fma2(bond2[2][b], kv, m2);
                m3 = fma2(bond2[3][b], kv, m3);
            }
            unsigned long long n0 = *reinterpret_cast<const unsigned long long*>(&nbsh[(w * G + 0) * ATOM_DIM + jp * 2]);
            unsigned long long n1 = *reinterpret_cast<const unsigned long long*>(&nbsh[(w * G + 1) * ATOM_DIM + jp * 2]);
            unsigned long long n2 = *reinterpret_cast<const unsigned long long*>(&nbsh[(w * G + 2) * ATOM_DIM + jp * 2]);
            unsigned long long n3 = *reinterpret_cast<const unsigned long long*>(&nbsh[(w * G + 3) * ATOM_DIM + jp * 2]);
            acc2[0] = fma2(m0, n0, acc2[0]);
            acc2[1] = fma2(m1, n1, acc2[1]);
            acc2[2] = fma2(m2, n2, acc2[2]);
            acc2[3] = fma2(m3, n3, acc2[3]);
        }

        // ---- scatter-add (coalesced: 32 lanes = 32 consecutive floats per edge) ----
        #pragma unroll
        for (int g = 0; g < G; g++) {
            int dst = dstsh[w * G + g];
            if (dst >= 0)
                atomicAdd(&out[(long long)dst * ATOM_DIM + lane], hsum2(acc2[g]));
        }
    }
}

extern "C" void kernel_launch(void* const* d_in, const int* in_sizes, int n_in,
                              void* d_out, int out_size) {
    const float* atom = (const float*)d_in[0];
    const float* bond = (const float*)d_in[1];
    const int*   pair = (const int*)d_in[2];
    const float* Kmat = (const float*)d_in[3];
    const float* bias = (const float*)d_in[4];
    float*       out  = (float*)d_out;

    const int n_edges  = in_sizes[1] / BOND_DIM;
    const int n_passes = (n_edges + EPP - 1) / EPP;

    cudaFuncSetAttribute(edge_network_kernel,
                         cudaFuncAttributeMaxDynamicSharedMemorySize, SMEM_BYTES);

    // Output is poisoned; zero it (memset node is graph-capturable, same stream => ordered).
    cudaMemsetAsync(d_out, 0, (size_t)out_size * sizeof(float), 0);

    int grid = n_passes < 592 ? n_passes : 592;
    edge_network_kernel<<<grid, NTHREADS, SMEM_BYTES>>>(atom, bond, pair, Kmat, bias, out,
                                                        n_edges, n_passes);
}

// round 7
// speedup vs baseline: 2.4579x; 2.4579x over previous
#include <cuda_runtime.h>
#include <stdint.h>

// EdgeNetwork via register-fragment bf16 mma.sync (legacy HMMA path; tcgen05 is
// unavailable because the harness PTX target is sm_103, not sm_103a).
//
//   B'[n][k], n in [0,544): n<512 -> B'[n][k] = Kmat[n*32+k]   (reshape(K,512,32))
//                           n>=512 -> bias[(n-512)*32+k]       (reshape(bias,32,32))
//   Per edge e: y[e,i] = sum_{blk=0..16} w[e,blk] * sum_j nb[e,j] * B'[blk*32+i][j]
//   with w[e,blk] = bond[e,blk] for blk<16, and 1.0 for blk=16 (bias block).
//   out = segment_sum(y, src)
//
// Precision: bf16 2-term split by truncation; C = Ahi Bhi + Alo Bhi + Ahi Blo
// accumulated in fp32 by the tensor core (rel err ~3e-5 << 1e-3 tolerance).
//
// atom (Na,32) f32, bond (E,16) f32, pair (E,2) int32, K (16,1024) f32,
// bias (1024) f32, out (Na,32) f32.

#define NTH    384
#define NWARPS 12
#define GRID_X 148
#define NBLK   17

#define BF_BYTES  (NBLK * 4 * 4 * 32 * 8)   // 69632: Bfrag[blk][n8][v][lane] uint2
#define NB_STRIDE 36                        // f32 row stride (144B, 16B-aligned rows)
#define NB_BYTES  (32 * NB_STRIDE * 4)      // 4608 per warp (nb staging, reused for y)
#define BD_STRIDE 20                        // f32 row stride (80B, 16B-aligned rows)
#define BD_BYTES  (32 * BD_STRIDE * 4)      // 2560 per warp
#define DST_BYTES (32 * 4)

#define OFF_NB(wid)  (BF_BYTES + (wid) * NB_BYTES)
#define OFF_BD(wid)  (BF_BYTES + NWARPS * NB_BYTES + (wid) * BD_BYTES)
#define OFF_DS(wid)  (BF_BYTES + NWARPS * (NB_BYTES + BD_BYTES) + (wid) * DST_BYTES)
#define SMEM_BYTES   (BF_BYTES + NWARPS * (NB_BYTES + BD_BYTES + DST_BYTES))  // 157184

__device__ __forceinline__ uint32_t prmt7632(uint32_t a, uint32_t b) {
    uint32_t r;
    asm("prmt.b32 %0, %1, %2, 0x7632;" : "=r"(r) : "r"(a), "r"(b));
    return r;  // {hi16(b), hi16(a)}: lower half = truncated-bf16(a)
}
__device__ __forceinline__ uint32_t pack_bf16x2(float upper, float lower) {
    uint32_t r;
    asm("cvt.rn.bf16x2.f32 %0, %1, %2;" : "=r"(r) : "f"(upper), "f"(lower));
    return r;
}

#define MMA16816(c0, c1, c2, c3, a0, a1, a2, a3, b0, b1)                        \
    asm volatile(                                                               \
        "mma.sync.aligned.m16n8k16.row.col.f32.bf16.bf16.f32 "                  \
        "{%0,%1,%2,%3}, {%4,%5,%6,%7}, {%8,%9}, {%0,%1,%2,%3};"                 \
        : "+f"(c0), "+f"(c1), "+f"(c2), "+f"(c3)                                \
        : "r"(a0), "r"(a1), "r"(a2), "r"(a3), "r"(b0), "r"(b1))

__global__ __launch_bounds__(NTH)
void edge_network_hmma(const float* __restrict__ atom,
                       const float* __restrict__ bond,
                       const int* __restrict__ pair,
                       const float* __restrict__ Kmat,
                       const float* __restrict__ bias,
                       float* __restrict__ out,
                       int n_edges, int n_wtiles)
{
    extern __shared__ __align__(16) char smem[];
    const int tid = threadIdx.x;
    const int w = tid >> 5, lane = tid & 31;

    // ---- one-time: build B fragment table in exact m16n8k16 B-operand order ----
    // idx = blk*512 + n8*128 + v*32 + lane;  v: 0=hi k0-15, 1=hi k16-31, 2=lo k0-15, 3=lo k16-31
    for (int idx = tid; idx < NBLK * 512; idx += NTH) {
        int li  = idx & 31;
        int v   = (idx >> 5) & 3;
        int n8  = (idx >> 7) & 3;
        int blk = idx >> 9;
        int n   = blk * 32 + n8 * 8 + (li >> 2);
        int kb  = (v & 1) * 16 + (li & 3) * 2;
        const float* src = (n < 512) ? (Kmat + n * 32) : (bias + (n - 512) * 32);
        float f0 = src[kb], f1 = src[kb + 1], f2 = src[kb + 8], f3 = src[kb + 9];
        uint2 r;
        if ((v >> 1) == 0) {  // hi: truncated bf16
            r.x = prmt7632(__float_as_uint(f0), __float_as_uint(f1));
            r.y = prmt7632(__float_as_uint(f2), __float_as_uint(f3));
        } else {              // lo: residual, rn-rounded bf16
            float l0 = f0 - __uint_as_float(__float_as_uint(f0) & 0xFFFF0000u);
            float l1 = f1 - __uint_as_float(__float_as_uint(f1) & 0xFFFF0000u);
            float l2 = f2 - __uint_as_float(__float_as_uint(f2) & 0xFFFF0000u);
            float l3 = f3 - __uint_as_float(__float_as_uint(f3) & 0xFFFF0000u);
            r.x = pack_bf16x2(l1, l0);
            r.y = pack_bf16x2(l3, l2);
        }
        reinterpret_cast<uint2*>(smem)[idx] = r;
    }
    __syncthreads();

    float* nbsh  = (float*)(smem + OFF_NB(w));  // [32][36], reused as y-tile
    float* bdsh  = (float*)(smem + OFF_BD(w));  // [32][20], col 16 = 1.0 (bias weight)
    int*   dstw  = (int*)(smem + OFF_DS(w));
    const uint2* bft = reinterpret_cast<const uint2*>(smem);

    const int warp_gid = blockIdx.x * NWARPS + w;
    const int wstep    = gridDim.x * NWARPS;

    for (int t = warp_gid; t < n_wtiles; t += wstep) {
        const int e0 = t * 32;

        // ---- stage: 32 nb rows (gather) + bond rows; 2 lanes per edge, 2 passes ----
        #pragma unroll
        for (int p = 0; p < 2; p++) {
            int el = p * 16 + (lane >> 1);
            int e  = e0 + el;
            int hf = lane & 1;
            const float4 z = make_float4(0.f, 0.f, 0.f, 0.f);
            const float* asrc = nullptr;
            if (e < n_edges) asrc = atom + (size_t)pair[2 * e + 1] * 32 + hf * 16;
            #pragma unroll
            for (int q = 0; q < 4; q++) {
                float4 vv = asrc ? *reinterpret_cast<const float4*>(asrc + q * 4) : z;
                *reinterpret_cast<float4*>(&nbsh[el * NB_STRIDE + hf * 16 + q * 4]) = vv;
            }
            #pragma unroll
            for (int q = 0; q < 2; q++) {
                float4 vv = (e < n_edges)
                    ? *reinterpret_cast<const float4*>(bond + (size_t)e * 16 + hf * 8 + q * 4) : z;
                *reinterpret_cast<float4*>(&bdsh[el * BD_STRIDE + hf * 8 + q * 4]) = vv;
            }
        }
        {
            int e = e0 + lane;
            dstw[lane] = (e < n_edges) ? pair[2 * e] : -1;
            bdsh[lane * BD_STRIDE + 16] = 1.0f;  // bias-block weight
        }
        __syncwarp();

        // ---- build A fragments (hi/lo bf16 split), 2 row-groups x 2 k-chunks ----
        uint32_t ahi[2][8], alo[2][8];
        #pragma unroll
        for (int g = 0; g < 2; g++)
            #pragma unroll
            for (int kc = 0; kc < 2; kc++)
                #pragma unroll
                for (int q = 0; q < 4; q++) {
                    int r = g * 16 + (lane >> 2) + (q & 1) * 8;
                    int c = kc * 16 + (lane & 3) * 2 + (q >> 1) * 8;
                    float2 f = *reinterpret_cast<const float2*>(&nbsh[r * NB_STRIDE + c]);
                    uint32_t u0 = __float_as_uint(f.x), u1 = __float_as_uint(f.y);
                    float l0 = f.x - __uint_as_float(u0 & 0xFFFF0000u);
                    float l1 = f.y - __uint_as_float(u1 & 0xFFFF0000u);
                    ahi[g][kc * 4 + q] = prmt7632(u0, u1);
                    alo[g][kc * 4 + q] = pack_bf16x2(l1, l0);
                }
        __syncwarp();  // all lanes done reading nbsh; safe to reuse it for y

        float yac[2][16];
        #pragma unroll
        for (int g = 0; g < 2; g++)
            #pragma unroll
            for (int i = 0; i < 16; i++) yac[g][i] = 0.f;

        // ---- main loop: 17 column-blocks; per block 48 MMAs + bond-weighted merge ----
        #pragma unroll 1
        for (int blk = 0; blk < NBLK; blk++) {
            float w00 = bdsh[((lane >> 2) + 0)  * BD_STRIDE + blk];
            float w01 = bdsh[((lane >> 2) + 8)  * BD_STRIDE + blk];
            float w10 = bdsh[((lane >> 2) + 16) * BD_STRIDE + blk];
            float w11 = bdsh[((lane >> 2) + 24) * BD_STRIDE + blk];
            #pragma unroll
            for (int n8 = 0; n8 < 4; n8++) {
                const uint2* bp = bft + ((blk * 4 + n8) * 4) * 32 + lane;
                uint2 v0 = bp[0], v1 = bp[32], v2 = bp[64], v3 = bp[96];
                #pragma unroll
                for (int g = 0; g < 2; g++) {
                    float c0 = 0.f, c1 = 0.f, c2 = 0.f, c3 = 0.f;
                    MMA16816(c0, c1, c2, c3, ahi[g][0], ahi[g][1], ahi[g][2], ahi[g][3], v0.x, v0.y);
                    MMA16816(c0, c1, c2, c3, ahi[g][4], ahi[g][5], ahi[g][6], ahi[g][7], v1.x, v1.y);
                    MMA16816(c0, c1, c2, c3, alo[g][0], alo[g][1], alo[g][2], alo[g][3], v0.x, v0.y);
                    MMA16816(c0, c1, c2, c3, alo[g][4], alo[g][5], alo[g][6], alo[g][7], v1.x, v1.y);
                    MMA16816(c0, c1, c2, c3, ahi[g][0], ahi[g][1], ahi[g][2], ahi[g][3], v2.x, v2.y);
                    MMA16816(c0, c1, c2, c3, ahi[g][4], ahi[g][5], ahi[g][6], ahi[g][7], v3.x, v3.y);
                    float wa = g ? w10 : w00;
                    float wb = g ? w11 : w01;
                    yac[g][n8 * 4 + 0] = fmaf(wa, c0, yac[g][n8 * 4 + 0]);
                    yac[g][n8 * 4 + 1] = fmaf(wa, c1, yac[g][n8 * 4 + 1]);
                    yac[g][n8 * 4 + 2] = fmaf(wb, c2, yac[g][n8 * 4 + 2]);
                    yac[g][n8 * 4 + 3] = fmaf(wb, c3, yac[g][n8 * 4 + 3]);
                }
            }
        }

        // ---- y fragments -> smem (reuse nbsh), then coalesced scatter-add ----
        #pragma unroll
        for (int g = 0; g < 2; g++)
            #pragma unroll
            for (int n8 = 0; n8 < 4; n8++) {
                int r0 = g * 16 + (lane >> 2);
                int c  = n8 * 8 + (lane & 3) * 2;
                *reinterpret_cast<float2*>(&nbsh[r0 * NB_STRIDE + c]) =
                    make_float2(yac[g][n8 * 4 + 0], yac[g][n8 * 4 + 1]);
                *reinterpret_cast<float2*>(&nbsh[(r0 + 8) * NB_STRIDE + c]) =
                    make_float2(yac[g][n8 * 4 + 2], yac[g][n8 * 4 + 3]);
            }
        __syncwarp();

        #pragma unroll 1
        for (int r = 0; r < 32; r++) {
            int d = dstw[r];
            if (d >= 0)
                atomicAdd(&out[(size_t)d * 32 + lane], nbsh[r * NB_STRIDE + lane]);
        }
        __syncwarp();  // finish reading nbsh before next tile's staging overwrites it
    }
}

extern "C" void kernel_launch(void* const* d_in, const int* in_sizes, int n_in,
                              void* d_out, int out_size) {
    const float* atom = (const float*)d_in[0];
    const float* bond = (const float*)d_in[1];
    const int*   pair = (const int*)d_in[2];
    const float* Kmat = (const float*)d_in[3];
    const float* bias = (const float*)d_in[4];
    float*       out  = (float*)d_out;

    const int n_edges  = in_sizes[1] / 16;
    const int n_wtiles = (n_edges + 31) / 32;

    cudaFuncSetAttribute(edge_network_hmma,
                         cudaFuncAttributeMaxDynamicSharedMemorySize, SMEM_BYTES);

    cudaMemsetAsync(d_out, 0, (size_t)out_size * sizeof(float), 0);

    int nblocks = (n_wtiles + NWARPS - 1) / NWARPS;
    if (nblocks > GRID_X) nblocks = GRID_X;
    edge_network_hmma<<<nblocks, NTH, SMEM_BYTES>>>(atom, bond, pair, Kmat, bias, out,
                                                    n_edges, n_wtiles);
}

// round 8
// speedup vs baseline: 2.6701x; 1.0864x over previous
#include <cuda_runtime.h>
#include <stdint.h>

// EdgeNetwork via register-fragment bf16 mma.sync (legacy HMMA path; tcgen05 is
// unavailable because the harness PTX target is sm_103, not sm_103a).
//
//   B'[n][k], n in [0,544): n<512 -> B'[n][k] = Kmat[n*32+k]   (reshape(K,512,32))
//                           n>=512 -> bias[(n-512)*32+k]       (reshape(bias,32,32))
//   Per edge e: y[e,i] = sum_{blk=0..16} w[e,blk] * sum_j nb[e,j] * B'[blk*32+i][j]
//   with w[e,blk] = bond[e,blk] for blk<16, and 1.0 for blk=16 (bias block).
//   out = segment_sum(y, src)
//
// Precision: bf16 2-term split by truncation; C = Ahi Bhi + Alo Bhi + Ahi Blo
// accumulated in fp32 by the tensor core (rel err ~1.4e-5, validated R7).
//
// atom (Na,32) f32, bond (E,16) f32, pair (E,2) int32, K (16,1024) f32,
// bias (1024) f32, out (Na,32) f32.

#define NTH    512
#define NWARPS 16
#define GRID_X 148
#define NBLK   17

#define BF_BYTES  (NBLK * 4 * 4 * 32 * 8)   // 69632: Bfrag[blk][n8][v][lane] uint2
#define NB_STRIDE 36                        // f32 row stride (144B, 16B-aligned rows)
#define NB_BYTES  (32 * NB_STRIDE * 4)      // 4608 per warp (nb staging, reused for y)
#define BD_STRIDE 20                        // f32 row stride (80B, 16B-aligned rows)
#define BD_BYTES  (32 * BD_STRIDE * 4)      // 2560 per warp
#define DST_BYTES (32 * 4)

#define OFF_NB(wid)  (BF_BYTES + (wid) * NB_BYTES)
#define OFF_BD(wid)  (BF_BYTES + NWARPS * NB_BYTES + (wid) * BD_BYTES)
#define OFF_DS(wid)  (BF_BYTES + NWARPS * (NB_BYTES + BD_BYTES) + (wid) * DST_BYTES)
#define SMEM_BYTES   (BF_BYTES + NWARPS * (NB_BYTES + BD_BYTES + DST_BYTES))  // 186368

__device__ __forceinline__ uint32_t prmt7632(uint32_t a, uint32_t b) {
    uint32_t r;
    asm("prmt.b32 %0, %1, %2, 0x7632;" : "=r"(r) : "r"(a), "r"(b));
    return r;  // {hi16(b), hi16(a)}: lower half = truncated-bf16(a)
}
__device__ __forceinline__ uint32_t pack_bf16x2(float upper, float lower) {
    uint32_t r;
    asm("cvt.rn.bf16x2.f32 %0, %1, %2;" : "=r"(r) : "f"(upper), "f"(lower));
    return r;
}

#define MMA16816(c0, c1, c2, c3, a0, a1, a2, a3, b0, b1)                        \
    asm volatile(                                                               \
        "mma.sync.aligned.m16n8k16.row.col.f32.bf16.bf16.f32 "                  \
        "{%0,%1,%2,%3}, {%4,%5,%6,%7}, {%8,%9}, {%0,%1,%2,%3};"                 \
        : "+f"(c0), "+f"(c1), "+f"(c2), "+f"(c3)                                \
        : "r"(a0), "r"(a1), "r"(a2), "r"(a3), "r"(b0), "r"(b1))

__global__ __launch_bounds__(NTH)
void edge_network_hmma(const float* __restrict__ atom,
                       const float* __restrict__ bond,
                       const int* __restrict__ pair,
                       const float* __restrict__ Kmat,
                       const float* __restrict__ bias,
                       float* __restrict__ out,
                       int n_edges, int n_wtiles)
{
    extern __shared__ __align__(16) char smem[];
    const int tid = threadIdx.x;
    const int w = tid >> 5, lane = tid & 31;

    // ---- one-time: build B fragment table in exact m16n8k16 B-operand order ----
    // idx = blk*512 + n8*128 + v*32 + lane;  v: 0=hi k0-15, 1=hi k16-31, 2=lo k0-15, 3=lo k16-31
    for (int idx = tid; idx < NBLK * 512; idx += NTH) {
        int li  = idx & 31;
        int v   = (idx >> 5) & 3;
        int n8  = (idx >> 7) & 3;
        int blk = idx >> 9;
        int n   = blk * 32 + n8 * 8 + (li >> 2);
        int kb  = (v & 1) * 16 + (li & 3) * 2;
        const float* src = (n < 512) ? (Kmat + n * 32) : (bias + (n - 512) * 32);
        float f0 = src[kb], f1 = src[kb + 1], f2 = src[kb + 8], f3 = src[kb + 9];
        uint2 r;
        if ((v >> 1) == 0) {  // hi: truncated bf16
            r.x = prmt7632(__float_as_uint(f0), __float_as_uint(f1));
            r.y = prmt7632(__float_as_uint(f2), __float_as_uint(f3));
        } else {              // lo: residual, rn-rounded bf16
            float l0 = f0 - __uint_as_float(__float_as_uint(f0) & 0xFFFF0000u);
            float l1 = f1 - __uint_as_float(__float_as_uint(f1) & 0xFFFF0000u);
            float l2 = f2 - __uint_as_float(__float_as_uint(f2) & 0xFFFF0000u);
            float l3 = f3 - __uint_as_float(__float_as_uint(f3) & 0xFFFF0000u);
            r.x = pack_bf16x2(l1, l0);
            r.y = pack_bf16x2(l3, l2);
        }
        reinterpret_cast<uint2*>(smem)[idx] = r;
    }
    __syncthreads();

    float* nbsh  = (float*)(smem + OFF_NB(w));  // [32][36], reused as y-tile
    float* bdsh  = (float*)(smem + OFF_BD(w));  // [32][20], col 16 = 1.0 (bias weight)
    int*   dstw  = (int*)(smem + OFF_DS(w));
    const uint2* bft = reinterpret_cast<const uint2*>(smem);

    const int warp_gid = blockIdx.x * NWARPS + w;
    const int wstep    = gridDim.x * NWARPS;

    for (int t = warp_gid; t < n_wtiles; t += wstep) {
        const int e0 = t * 32;

        // ---- stage: 32 nb rows (gather) + bond rows; 2 lanes per edge, 2 passes ----
        #pragma unroll
        for (int p = 0; p < 2; p++) {
            int el = p * 16 + (lane >> 1);
            int e  = e0 + el;
            int hf = lane & 1;
            const float4 z = make_float4(0.f, 0.f, 0.f, 0.f);
            const float* asrc = nullptr;
            if (e < n_edges) asrc = atom + (size_t)pair[2 * e + 1] * 32 + hf * 16;
            #pragma unroll
            for (int q = 0; q < 4; q++) {
                float4 vv = asrc ? *reinterpret_cast<const float4*>(asrc + q * 4) : z;
                *reinterpret_cast<float4*>(&nbsh[el * NB_STRIDE + hf * 16 + q * 4]) = vv;
            }
            #pragma unroll
            for (int q = 0; q < 2; q++) {
                float4 vv = (e < n_edges)
                    ? *reinterpret_cast<const float4*>(bond + (size_t)e * 16 + hf * 8 + q * 4) : z;
                *reinterpret_cast<float4*>(&bdsh[el * BD_STRIDE + hf * 8 + q * 4]) = vv;
            }
        }
        {
            int e = e0 + lane;
            dstw[lane] = (e < n_edges) ? pair[2 * e] : -1;
            bdsh[lane * BD_STRIDE + 16] = 1.0f;  // bias-block weight
        }
        __syncwarp();

        // ---- build A fragments (hi/lo bf16 split), 2 row-groups x 2 k-chunks ----
        uint32_t ahi[2][8], alo[2][8];
        #pragma unroll
        for (int g = 0; g < 2; g++)
            #pragma unroll
            for (int kc = 0; kc < 2; kc++)
                #pragma unroll
                for (int q = 0; q < 4; q++) {
                    int r = g * 16 + (lane >> 2) + (q & 1) * 8;
                    int c = kc * 16 + (lane & 3) * 2 + (q >> 1) * 8;
                    float2 f = *reinterpret_cast<const float2*>(&nbsh[r * NB_STRIDE + c]);
                    uint32_t u0 = __float_as_uint(f.x), u1 = __float_as_uint(f.y);
                    float l0 = f.x - __uint_as_float(u0 & 0xFFFF0000u);
                    float l1 = f.y - __uint_as_float(u1 & 0xFFFF0000u);
                    ahi[g][kc * 4 + q] = prmt7632(u0, u1);
                    alo[g][kc * 4 + q] = pack_bf16x2(l1, l0);
                }
        __syncwarp();  // all lanes done reading nbsh; safe to reuse it for y

        float yac[2][16];
        #pragma unroll
        for (int g = 0; g < 2; g++)
            #pragma unroll
            for (int i = 0; i < 16; i++) yac[g][i] = 0.f;

        // ---- main loop: 17 column-blocks; per block 48 MMAs + bond-weighted merge ----
        #pragma unroll 1
        for (int blk = 0; blk < NBLK; blk++) {
            float w00 = bdsh[((lane >> 2) + 0)  * BD_STRIDE + blk];
            float w01 = bdsh[((lane >> 2) + 8)  * BD_STRIDE + blk];
            float w10 = bdsh[((lane >> 2) + 16) * BD_STRIDE + blk];
            float w11 = bdsh[((lane >> 2) + 24) * BD_STRIDE + blk];
            #pragma unroll
            for (int n8 = 0; n8 < 4; n8++) {
                const uint2* bp = bft + ((blk * 4 + n8) * 4) * 32 + lane;
                uint2 v0 = bp[0], v1 = bp[32], v2 = bp[64], v3 = bp[96];
                #pragma unroll
                for (int g = 0; g < 2; g++) {
                    float c0 = 0.f, c1 = 0.f, c2 = 0.f, c3 = 0.f;
                    MMA16816(c0, c1, c2, c3, ahi[g][0], ahi[g][1], ahi[g][2], ahi[g][3], v0.x, v0.y);
                    MMA16816(c0, c1, c2, c3, ahi[g][4], ahi[g][5], ahi[g][6], ahi[g][7], v1.x, v1.y);
                    MMA16816(c0, c1, c2, c3, alo[g][0], alo[g][1], alo[g][2], alo[g][3], v0.x, v0.y);
                    MMA16816(c0, c1, c2, c3, alo[g][4], alo[g][5], alo[g][6], alo[g][7], v1.x, v1.y);
                    MMA16816(c0, c1, c2, c3, ahi[g][0], ahi[g][1], ahi[g][2], ahi[g][3], v2.x, v2.y);
                    MMA16816(c0, c1, c2, c3, ahi[g][4], ahi[g][5], ahi[g][6], ahi[g][7], v3.x, v3.y);
                    float wa = g ? w10 : w00;
                    float wb = g ? w11 : w01;
                    yac[g][n8 * 4 + 0] = fmaf(wa, c0, yac[g][n8 * 4 + 0]);
                    yac[g][n8 * 4 + 1] = fmaf(wa, c1, yac[g][n8 * 4 + 1]);
                    yac[g][n8 * 4 + 2] = fmaf(wb, c2, yac[g][n8 * 4 + 2]);
                    yac[g][n8 * 4 + 3] = fmaf(wb, c3, yac[g][n8 * 4 + 3]);
                }
            }
        }

        // ---- y fragments -> smem (reuse nbsh) ----
        #pragma unroll
        for (int g = 0; g < 2; g++)
            #pragma unroll
            for (int n8 = 0; n8 < 4; n8++) {
                int r0 = g * 16 + (lane >> 2);
                int c  = n8 * 8 + (lane & 3) * 2;
                *reinterpret_cast<float2*>(&nbsh[r0 * NB_STRIDE + c]) =
                    make_float2(yac[g][n8 * 4 + 0], yac[g][n8 * 4 + 1]);
                *reinterpret_cast<float2*>(&nbsh[(r0 + 8) * NB_STRIDE + c]) =
                    make_float2(yac[g][n8 * 4 + 2], yac[g][n8 * 4 + 3]);
            }
        __syncwarp();

        // ---- scatter-add via vector red: 8 lanes x v4.f32 per edge, 4 edges/iter ----
        #pragma unroll 1
        for (int rr = 0; rr < 8; rr++) {
            int el = rr * 4 + (lane >> 3);
            int c  = (lane & 7) * 4;
            int d  = dstw[el];
            if (d >= 0) {
                float4 v = *reinterpret_cast<const float4*>(&nbsh[el * NB_STRIDE + c]);
                asm volatile("red.global.add.v4.f32 [%0], {%1,%2,%3,%4};"
                             :: "l"(out + (size_t)d * 32 + c),
                                "f"(v.x), "f"(v.y), "f"(v.z), "f"(v.w)
                             : "memory");
            }
        }
        __syncwarp();  // finish reading nbsh before next tile's staging overwrites it
    }
}

extern "C" void kernel_launch(void* const* d_in, const int* in_sizes, int n_in,
                              void* d_out, int out_size) {
    const float* atom = (const float*)d_in[0];
    const float* bond = (const float*)d_in[1];
    const int*   pair = (const int*)d_in[2];
    const float* Kmat = (const float*)d_in[3];
    const float* bias = (const float*)d_in[4];
    float*       out  = (float*)d_out;

    const int n_edges  = in_sizes[1] / 16;
    const int n_wtiles = (n_edges + 31) / 32;

    cudaFuncSetAttribute(edge_network_hmma,
                         cudaFuncAttributeMaxDynamicSharedMemorySize, SMEM_BYTES);

    cudaMemsetAsync(d_out, 0, (size_t)out_size * sizeof(float), 0);

    int nblocks = (n_wtiles + NWARPS - 1) / NWARPS;
    if (nblocks > GRID_X) nblocks = GRID_X;
    edge_network_hmma<<<nblocks, NTH, SMEM_BYTES>>>(atom, bond, pair, Kmat, bias, out,
                                                    n_edges, n_wtiles);
}